// round 6
// baseline (speedup 1.0000x reference)
#include <cuda_runtime.h>
#include <math.h>
#include <stdint.h>

// Problem dims
#define Q    64
#define SQ   32
#define CC   256
#define SC   256
#define H    768
#define D    128
#define QT   31
#define CT   255
#define QROWS (Q*QT)     // 1984
#define CROWS (CC*CT)    // 65280
#define NROWS (QROWS+CROWS)

// Scratch: projected+normalized token embeddings (tf32-rounded), ROW-MAJOR.
__device__ float g_col[(size_t)NROWS * D];
__device__ float g_denom[Q];

// ---------------------------------------------------------------------------
// helpers
// ---------------------------------------------------------------------------
__device__ __forceinline__ float f2tf(float x) {
    uint32_t r;
    asm("cvt.rna.tf32.f32 %0, %1;" : "=r"(r) : "f"(x));
    return __uint_as_float(r);
}
__device__ __forceinline__ void mma_tf32(float* c, const uint32_t* a, const uint32_t* b) {
    asm volatile(
        "mma.sync.aligned.m16n8k8.row.col.f32.tf32.tf32.f32 "
        "{%0,%1,%2,%3},{%4,%5,%6,%7},{%8,%9},{%0,%1,%2,%3};\n"
        : "+f"(c[0]), "+f"(c[1]), "+f"(c[2]), "+f"(c[3])
        : "r"(a[0]), "r"(a[1]), "r"(a[2]), "r"(a[3]), "r"(b[0]), "r"(b[1]));
}
__device__ __forceinline__ uint32_t smem_u32(const void* p) {
    uint32_t a;
    asm("{ .reg .u64 t; cvta.to.shared.u64 t, %1; cvt.u32.u64 %0, t; }" : "=r"(a) : "l"(p));
    return a;
}
#define CP_ASYNC16(dst_u32, src_ptr) \
    asm volatile("cp.async.ca.shared.global [%0], [%1], 16;" :: "r"(dst_u32), "l"(src_ptr))
#define CP_COMMIT() asm volatile("cp.async.commit_group;" ::: "memory")
#define CP_WAIT1()  asm volatile("cp.async.wait_group 1;" ::: "memory")
#define CP_WAIT0()  asm volatile("cp.async.wait_group 0;" ::: "memory")

// ---------------------------------------------------------------------------
// Kernel 1: pooled vectors (fp32 exact)
// ---------------------------------------------------------------------------
__global__ void pooled_kernel(const float* __restrict__ qh,
                              const float* __restrict__ ch,
                              const int*   __restrict__ qm,
                              const int*   __restrict__ cm,
                              float* __restrict__ out) {
    int r = blockIdx.x;
    const float* src;
    float mask;
    float* dst;
    if (r < Q) {
        src  = qh + (size_t)r * SQ * H;
        mask = (float)qm[r * SQ];
        dst  = out + Q * CC + (size_t)r * H;
    } else {
        int c = r - Q;
        src  = ch + (size_t)c * SC * H;
        mask = (float)cm[c * SC];
        dst  = out + Q * CC + Q * H + (size_t)c * H;
    }
    __shared__ float red[8];
    int t = threadIdx.x;
    float v[3];
    float s = 0.f;
#pragma unroll
    for (int it = 0; it < 3; it++) {
        float x = src[t + it * 256] * mask;
        v[it] = x;
        s += x * x;
    }
#pragma unroll
    for (int o = 16; o; o >>= 1) s += __shfl_xor_sync(0xffffffffu, s, o);
    if ((t & 31) == 0) red[t >> 5] = s;
    __syncthreads();
    if (t < 8) {
        float ss = red[t];
#pragma unroll
        for (int o = 4; o; o >>= 1) ss += __shfl_xor_sync(0xffu, ss, o);
        if (t == 0) red[0] = ss;
    }
    __syncthreads();
    float inv = 1.f / fmaxf(sqrtf(red[0]), 1e-12f);
#pragma unroll
    for (int it = 0; it < 3; it++) dst[t + it * 256] = v[it] * inv;
}

// ---------------------------------------------------------------------------
// Kernel 2: denominators
// ---------------------------------------------------------------------------
__global__ void denom_kernel(const int* __restrict__ qm) {
    int q = threadIdx.x;
    if (q < Q) {
        int s = 0;
        for (int i = 1; i < SQ; i++) s += qm[q * SQ + i];
        g_denom[q] = (float)s;
    }
}

// ---------------------------------------------------------------------------
// Kernel 3: projection + l2norm (unchanged from round 4/5)
// ---------------------------------------------------------------------------
#define P_SA 36
#define P_SW 132
__global__ __launch_bounds__(256) void proj_kernel(const float* __restrict__ qh,
                                                   const float* __restrict__ ch,
                                                   const float* __restrict__ Wm,
                                                   const float* __restrict__ bias,
                                                   const int*   __restrict__ qm,
                                                   const int*   __restrict__ cm) {
    __shared__ float As[2][64 * P_SA];
    __shared__ float Ws[2][32 * P_SW];
    __shared__ float rowsq[64][4];
    __shared__ float invn[64];
    __shared__ const float* srcp[64];
    __shared__ float mk[64];

    int t = threadIdx.x;
    int w = t >> 5, lane = t & 31, g = lane >> 2, tg = lane & 3;
    int mw = w & 1, nw = w >> 1;
    int m_warp = mw * 32, n_warp = nw * 32;

    if (t < 64) {
        int r = blockIdx.x * 64 + t;
        if (r < QROWS) {
            int q = r / QT, i = r - q * QT;
            srcp[t] = qh + (size_t)(q * SQ + i + 1) * H;
            mk[t]   = (float)qm[q * SQ + i + 1];
        } else {
            int rc = r - QROWS;
            int c = rc / CT, j = rc - c * CT;
            srcp[t] = ch + (size_t)(c * SC + j + 1) * H;
            mk[t]   = (float)cm[c * SC + j + 1];
        }
    }

    float binit[4][2];
#pragma unroll
    for (int nt4 = 0; nt4 < 4; nt4++) {
        int col = n_warp + nt4 * 8 + 2 * tg;
        binit[nt4][0] = bias[col];
        binit[nt4][1] = bias[col + 1];
    }
    __syncthreads();

    uint32_t sA0 = smem_u32(&As[0][0]), sA1 = smem_u32(&As[1][0]);
    uint32_t sW0 = smem_u32(&Ws[0][0]), sW1 = smem_u32(&Ws[1][0]);

#define STAGE(bufA, bufW, KT) do {                                              \
    _Pragma("unroll")                                                           \
    for (int itc = 0; itc < 2; itc++) {                                         \
        int idx = t + itc * 256;                                                \
        int m = idx >> 3, k4 = idx & 7;                                         \
        CP_ASYNC16((bufA) + (m * P_SA + k4 * 4) * 4, srcp[m] + (KT) + k4 * 4);  \
    }                                                                           \
    _Pragma("unroll")                                                           \
    for (int itc = 0; itc < 4; itc++) {                                         \
        int idx = t + itc * 256;                                                \
        int k = idx >> 5, d4 = idx & 31;                                        \
        CP_ASYNC16((bufW) + (k * P_SW + d4 * 4) * 4,                            \
                   Wm + (size_t)((KT) + k) * D + d4 * 4);                       \
    }                                                                           \
} while (0)

    STAGE(sA0, sW0, 0);
    CP_COMMIT();

    float acc[2][4][4];
#pragma unroll
    for (int mt = 0; mt < 2; mt++)
#pragma unroll
        for (int nt4 = 0; nt4 < 4; nt4++)
#pragma unroll
            for (int i = 0; i < 4; i++) acc[mt][nt4][i] = 0.f;

    for (int it = 0; it < 24; it++) {
        if (it < 23) {
            if (it & 1) STAGE(sA0, sW0, (it + 1) * 32);
            else        STAGE(sA1, sW1, (it + 1) * 32);
            CP_COMMIT();
            CP_WAIT1();
        } else {
            CP_WAIT0();
        }
        __syncthreads();
        const float* A = As[it & 1];
        const float* W = Ws[it & 1];
#pragma unroll
        for (int ks = 0; ks < 4; ks++) {
            int k0 = ks * 8;
            uint32_t afr[2][4], bfr[4][2];
#pragma unroll
            for (int mt = 0; mt < 2; mt++) {
                int base = m_warp + mt * 16;
                afr[mt][0] = __float_as_uint(A[(base + g)     * P_SA + k0 + tg]);
                afr[mt][1] = __float_as_uint(A[(base + g + 8) * P_SA + k0 + tg]);
                afr[mt][2] = __float_as_uint(A[(base + g)     * P_SA + k0 + tg + 4]);
                afr[mt][3] = __float_as_uint(A[(base + g + 8) * P_SA + k0 + tg + 4]);
            }
#pragma unroll
            for (int nt4 = 0; nt4 < 4; nt4++) {
                int col = n_warp + nt4 * 8 + g;
                bfr[nt4][0] = __float_as_uint(W[(k0 + tg)     * P_SW + col]);
                bfr[nt4][1] = __float_as_uint(W[(k0 + tg + 4) * P_SW + col]);
            }
#pragma unroll
            for (int mt = 0; mt < 2; mt++)
#pragma unroll
                for (int nt4 = 0; nt4 < 4; nt4++)
                    mma_tf32(acc[mt][nt4], afr[mt], bfr[nt4]);
        }
        __syncthreads();
    }

    float mrow[2][2];
#pragma unroll
    for (int mt = 0; mt < 2; mt++) {
        mrow[mt][0] = mk[m_warp + mt * 16 + g];
        mrow[mt][1] = mk[m_warp + mt * 16 + g + 8];
    }
#pragma unroll
    for (int mt = 0; mt < 2; mt++)
#pragma unroll
        for (int nt4 = 0; nt4 < 4; nt4++)
#pragma unroll
            for (int i = 0; i < 4; i++)
                acc[mt][nt4][i] = mrow[mt][i >> 1] * acc[mt][nt4][i] + binit[nt4][i & 1];

    float pr[2][2];
#pragma unroll
    for (int mt = 0; mt < 2; mt++)
#pragma unroll
        for (int h = 0; h < 2; h++) {
            float s = 0.f;
#pragma unroll
            for (int nt4 = 0; nt4 < 4; nt4++) {
                float c0 = acc[mt][nt4][2 * h], c1 = acc[mt][nt4][2 * h + 1];
                s += c0 * c0 + c1 * c1;
            }
            pr[mt][h] = s;
        }
#pragma unroll
    for (int off = 1; off <= 2; off <<= 1) {
#pragma unroll
        for (int mt = 0; mt < 2; mt++)
#pragma unroll
            for (int h = 0; h < 2; h++)
                pr[mt][h] += __shfl_xor_sync(0xffffffffu, pr[mt][h], off);
    }
    if (tg == 0) {
#pragma unroll
        for (int mt = 0; mt < 2; mt++)
#pragma unroll
            for (int h = 0; h < 2; h++)
                rowsq[m_warp + mt * 16 + g + 8 * h][nw] = pr[mt][h];
    }
    __syncthreads();
    if (t < 64) {
        float s = rowsq[t][0] + rowsq[t][1] + rowsq[t][2] + rowsq[t][3];
        invn[t] = 1.f / fmaxf(sqrtf(s), 1e-12f);
    }
    __syncthreads();

    size_t gbase = (size_t)blockIdx.x * 64;
#pragma unroll
    for (int mt = 0; mt < 2; mt++)
#pragma unroll
        for (int h = 0; h < 2; h++) {
            int r = m_warp + mt * 16 + g + 8 * h;
            float inv = invn[r];
            float* dst = g_col + (gbase + r) * D;
#pragma unroll
            for (int nt4 = 0; nt4 < 4; nt4++) {
                int col = n_warp + nt4 * 8 + 2 * tg;
                float2 v;
                v.x = f2tf(acc[mt][nt4][2 * h]     * inv);
                v.y = f2tf(acc[mt][nt4][2 * h + 1] * inv);
                *(float2*)(dst + col) = v;
            }
        }
#undef STAGE
}

// ---------------------------------------------------------------------------
// Kernel 4: fused maxsim — A-RESIDENT, B K-HALF DOUBLE-BUFFERED STREAM.
// Block = (query tile qt, doc-group of 8). Grid (16, 32) = 512 blocks.
// A (124 rows pad 128 x 128k) loaded once. Per doc: 2 K-halves of B
// (256 rows x 64k, 69.6 KB) double-buffered via cp.async; acc persists
// across halves; fused full-doc row-max epilogue (overlaps next prefetch).
// 512 threads, 16 warps = 2(M) x 8(N), warp tile 64x32, acc 64 regs.
// smem: A 128x132 + 2x B 256x68 + red = ~211 KB, 1 CTA/SM.
// ---------------------------------------------------------------------------
#define MS_SA 132
#define MS_SB 68
#define MSA_FLOATS (128 * MS_SA)
#define MSB_FLOATS (256 * MS_SB)
#define MS_SMEM_FLOATS (MSA_FLOATS + 2 * MSB_FLOATS + 8 * 128 + 128)
#define MS_SMEM_BYTES  (MS_SMEM_FLOATS * 4)

__global__ __launch_bounds__(512, 1) void maxsim_kernel(float* __restrict__ out) {
    extern __shared__ float sm[];
    float* As     = sm;                        // [m=128][k=128] stride 132
    float* Bs0    = sm + MSA_FLOATS;           // [n=256][k=64] stride 68
    float* Bs1    = Bs0 + MSB_FLOATS;
    float* red    = Bs1 + MSB_FLOATS;          // [8][128]
    float* rowmax = red + 8 * 128;             // [128]

    int t = threadIdx.x;
    int w = t >> 5, lane = t & 31, g = lane >> 2, tg = lane & 3;
    int mw = w & 1, nw = w >> 1;               // 2 M-warps, 8 N-warps
    int m_warp = mw * 64, n_warp = nw * 32;

    int qt = blockIdx.x;                       // query tile 0..15
    int bg = blockIdx.y;                       // doc group 0..31 (8 docs each)
    int d0 = bg * 8;

    // Zero A pad rows (124..127) so padded-row mmas stay finite.
    if (t < 132) {
#pragma unroll
        for (int m = 124; m < 128; m++) As[m * MS_SA + t] = 0.f;
    }

    // Stage A once: 124 rows x 32 float4 = 3968 chunks (8/thread).
    const float* abase = g_col + (size_t)qt * 124 * D;
#pragma unroll
    for (int j = 0; j < 8; j++) {
        int idx = t + j * 512;
        if (idx < 3968) {
            int m = idx >> 5, k4 = idx & 31;
            CP_ASYNC16(smem_u32(&As[m * MS_SA + k4 * 4]), abase + (size_t)m * D + k4 * 4);
        }
    }
    CP_COMMIT();

    // Stage B k-half (buffer, doc, kh): 256 rows x 16 float4 = 4096 chunks.
#define STAGEB(BUF, DOC, KH) do {                                                \
    const float* src = g_col + (size_t)(QROWS + (size_t)(DOC) * CT) * D + (KH) * 64; \
    _Pragma("unroll")                                                            \
    for (int j = 0; j < 8; j++) {                                                \
        int idx = t + j * 512;                                                   \
        int n = idx >> 4, k4 = idx & 15;                                         \
        if (n < CT)                                                              \
            CP_ASYNC16(smem_u32(&(BUF)[n * MS_SB + k4 * 4]), src + (size_t)n * D + k4 * 4); \
    }                                                                            \
} while (0)

    STAGEB(Bs0, d0, 0);
    CP_COMMIT();
    STAGEB(Bs1, d0, 1);
    CP_COMMIT();

    for (int d = 0; d < 8; d++) {
        int cdoc = d0 + d;
        float acc[4][4][4];
#pragma unroll
        for (int mt = 0; mt < 4; mt++)
#pragma unroll
            for (int nt = 0; nt < 4; nt++)
#pragma unroll
                for (int k = 0; k < 4; k++) acc[mt][nt][k] = 0.f;

#pragma unroll
        for (int kh = 0; kh < 2; kh++) {
            int hc = d * 2 + kh;
            CP_WAIT1();                       // half hc landed (hc+1 may fly)
            __syncthreads();
            const float* B = (hc & 1) ? Bs1 : Bs0;
            int kbase = kh * 64;

#pragma unroll
            for (int ks = 0; ks < 8; ks++) {
                int k0 = ks * 8;
                uint32_t afr[4][4], bfr[4][2];
#pragma unroll
                for (int mt = 0; mt < 4; mt++) {
                    int base = m_warp + mt * 16;
                    afr[mt][0] = __float_as_uint(As[(base + g)     * MS_SA + kbase + k0 + tg]);
                    afr[mt][1] = __float_as_uint(As[(base + g + 8) * MS_SA + kbase + k0 + tg]);
                    afr[mt][2] = __float_as_uint(As[(base + g)     * MS_SA + kbase + k0 + tg + 4]);
                    afr[mt][3] = __float_as_uint(As[(base + g + 8) * MS_SA + kbase + k0 + tg + 4]);
                }
#pragma unroll
                for (int nt = 0; nt < 4; nt++) {
                    int n = n_warp + nt * 8 + g;
                    bfr[nt][0] = __float_as_uint(B[n * MS_SB + k0 + tg]);
                    bfr[nt][1] = __float_as_uint(B[n * MS_SB + k0 + tg + 4]);
                }
#pragma unroll
                for (int mt = 0; mt < 4; mt++)
#pragma unroll
                    for (int nt = 0; nt < 4; nt++)
                        mma_tf32(acc[mt][nt], afr[mt], bfr[nt]);
            }
            __syncthreads();                  // all warps done reading this buffer
            if (hc + 2 <= 15) {               // refill it with half hc+2
                int nd = (hc + 2) >> 1, nk = (hc + 2) & 1;
                if (hc & 1) STAGEB(Bs1, d0 + nd, nk);
                else        STAGEB(Bs0, d0 + nd, nk);
                CP_COMMIT();
            }
        }

        // Fused row-max epilogue (guard padded col j=255; overlaps prefetch).
        float rp[4][2];
#pragma unroll
        for (int mt = 0; mt < 4; mt++) { rp[mt][0] = -INFINITY; rp[mt][1] = -INFINITY; }
#pragma unroll
        for (int mt = 0; mt < 4; mt++)
#pragma unroll
            for (int nt = 0; nt < 4; nt++)
#pragma unroll
                for (int k = 0; k < 4; k++) {
                    int j = n_warp + nt * 8 + 2 * tg + (k & 1);
                    if (j < CT) rp[mt][k >> 1] = fmaxf(rp[mt][k >> 1], acc[mt][nt][k]);
                }
#pragma unroll
        for (int off = 1; off <= 2; off <<= 1)
#pragma unroll
            for (int mt = 0; mt < 4; mt++)
#pragma unroll
                for (int h = 0; h < 2; h++)
                    rp[mt][h] = fmaxf(rp[mt][h], __shfl_xor_sync(0xffffffffu, rp[mt][h], off));
        if (tg == 0) {
#pragma unroll
            for (int mt = 0; mt < 4; mt++)
#pragma unroll
                for (int h = 0; h < 2; h++)
                    red[nw * 128 + m_warp + mt * 16 + g + 8 * h] = rp[mt][h];
        }
        __syncthreads();
        if (t < 124) {
            float mx = red[t];
#pragma unroll
            for (int r8 = 1; r8 < 8; r8++) mx = fmaxf(mx, red[r8 * 128 + t]);
            rowmax[t] = mx;
        }
        __syncthreads();
        if (t < 4) {
            int q = qt * 4 + t;
            float s = 0.f;
#pragma unroll
            for (int k = 0; k < 31; k++) s += rowmax[t * 31 + k];
            out[q * CC + cdoc] = s / g_denom[q];
        }
        // next CP_WAIT1+sync at loop top guards red/rowmax reuse
    }
#undef STAGEB
}

// ---------------------------------------------------------------------------
extern "C" void kernel_launch(void* const* d_in, const int* in_sizes, int n_in,
                              void* d_out, int out_size) {
    const float* qh  = (const float*)d_in[0];
    const float* ch  = (const float*)d_in[1];
    const float* Wm  = (const float*)d_in[2];
    const float* bia = (const float*)d_in[3];
    const int*   qm  = (const int*)d_in[4];
    const int*   cm  = (const int*)d_in[5];
    float* out = (float*)d_out;

    cudaFuncSetAttribute(maxsim_kernel,
                         cudaFuncAttributeMaxDynamicSharedMemorySize,
                         MS_SMEM_BYTES);

    pooled_kernel<<<Q + CC, 256>>>(qh, ch, qm, cm, out);
    denom_kernel<<<1, 64>>>(qm);
    proj_kernel<<<NROWS / 64, 256>>>(qh, ch, Wm, bia, qm, cm);
    maxsim_kernel<<<dim3(16, 32), 512, MS_SMEM_BYTES>>>(out);
}